// round 16
// baseline (speedup 1.0000x reference)
#include <cuda_runtime.h>
#include <cuda_bf16.h>

#define HID 4096
#define MH 16384             // 4 * HIDDEN
#define TOK 2
#define NT 256
#define NWARP (NT / 32)      // 8
#define NACC (TOK * 5)       // 10
#define NK (MH / 4 / NT)     // 16 float4-iterations per token
#define F4H (HID / 4)        // 1024
#define NQ (TOK * 4)         // 8 phase-2 groups (token-major)

__device__ __forceinline__ float bflo(unsigned u) {   // low bf16 -> f32
    return __uint_as_float(u << 16);
}
__device__ __forceinline__ float bfhi(unsigned u) {   // high bf16 -> f32
    return __uint_as_float(u & 0xFFFF0000u);
}
// round fp32 pair -> packed bf16x2 (RN, matches astype(bfloat16))
__device__ __forceinline__ unsigned pack_bf2(float a, float b) {
    __nv_bfloat162 p = __floats2bfloat162_rn(a, b);
    return *reinterpret_cast<unsigned*>(&p);
}

// issue the 4 stream-loads for phase-2 queue item q (t = q>>2, g = q&3)
__device__ __forceinline__ void p2_load(
    const float4* __restrict__ x4, size_t tok0, int q, int tid, float4* buf)
{
    const int t  = q >> 2;
    const int g  = q & 3;
    const int h4 = tid + g * NT;
    const float4* xp = x4 + (tok0 + t) * (MH / 4);
    buf[0] = __ldcs(xp + 0 * F4H + h4);
    buf[1] = __ldcs(xp + 1 * F4H + h4);
    buf[2] = __ldcs(xp + 2 * F4H + h4);
    buf[3] = __ldcs(xp + 3 * F4H + h4);
}

__global__ __launch_bounds__(NT, 4) void hchead_kernel(
    const float* __restrict__ x,
    const float* __restrict__ fn,
    const float* __restrict__ scale,
    const float* __restrict__ base,
    float* __restrict__ out)
{
    __shared__ float red[NWARP * NACC];

    const int tid  = threadIdx.x;
    const int warp = tid >> 5, lane = tid & 31;
    const size_t tok0 = (size_t)blockIdx.x * TOK;

    const float4* x4  = reinterpret_cast<const float4*>(x);
    const float4* fn4 = reinterpret_cast<const float4*>(fn);

    // acc: t*5+0 = sum(x^2), t*5+1+m = dot with fn[m]
    float acc[NACC];
#pragma unroll
    for (int i = 0; i < NACC; i++) acc[i] = 0.f;

    // ------- Phase 1: stream x (DRAM) + fn (L2), accumulate sums -------
#pragma unroll 4
    for (int k = 0; k < NK; k++) {          // 16 iterations
        const int f = tid + k * NT;         // float4 index (j = 4f)
        const float4 g0 = fn4[0 * (MH / 4) + f];
        const float4 g1 = fn4[1 * (MH / 4) + f];
        const float4 g2 = fn4[2 * (MH / 4) + f];
        const float4 g3 = fn4[3 * (MH / 4) + f];
        float4 v0 = x4[(tok0 + 0) * (MH / 4) + f];
        float4 v1 = x4[(tok0 + 1) * (MH / 4) + f];
#pragma unroll
        for (int t = 0; t < TOK; t++) {
            const float4 v = (t == 0) ? v0 : v1;
            const unsigned p0 = pack_bf2(v.x, v.y);
            const unsigned p1 = pack_bf2(v.z, v.w);
            const float x0 = bflo(p0), x1 = bfhi(p0);
            const float x2 = bflo(p1), x3 = bfhi(p1);
            acc[t * 5 + 0] += x0 * x0 + x1 * x1 + x2 * x2 + x3 * x3;
            acc[t * 5 + 1] += x0 * g0.x + x1 * g0.y + x2 * g0.z + x3 * g0.w;
            acc[t * 5 + 2] += x0 * g1.x + x1 * g1.y + x2 * g1.z + x3 * g1.w;
            acc[t * 5 + 3] += x0 * g2.x + x1 * g2.y + x2 * g2.z + x3 * g2.w;
            acc[t * 5 + 4] += x0 * g3.x + x1 * g3.y + x2 * g3.z + x3 * g3.w;
        }
    }

    // ------- Prefetch phase-2 groups 0,1 (fly under the reduction) -------
    float4 pf[3][4];
    p2_load(x4, tok0, 0, tid, pf[0]);
    p2_load(x4, tok0, 1, tid, pf[1]);

    // ------- Warp butterfly reduction of 10 partials -------
#pragma unroll
    for (int i = 0; i < NACC; i++) {
#pragma unroll
        for (int o = 16; o > 0; o >>= 1)
            acc[i] += __shfl_xor_sync(0xffffffffu, acc[i], o);
    }
    if (lane == 0) {
#pragma unroll
        for (int i = 0; i < NACC; i++) red[warp * NACC + i] = acc[i];
    }
    __syncthreads();        // red[] published — the ONLY block barrier here

    // ------- Prefetch group 2 (accs dead now, regs free) -------
    p2_load(x4, tok0, 2, tid, pf[2]);

    // ------- Warp-local combine: lane parity picks the token -------
    // Every warp computes both tokens' weights independently; no 2nd barrier.
    float wA[4], wB[4];
    {
        const int myt = lane & 1;           // token handled by this lane
        float ss = 0.f, d0 = 0.f, d1 = 0.f, d2 = 0.f, d3 = 0.f;
#pragma unroll
        for (int w = 0; w < NWARP; w++) {
            ss += red[w * NACC + myt * 5 + 0];
            d0 += red[w * NACC + myt * 5 + 1];
            d1 += red[w * NACC + myt * 5 + 2];
            d2 += red[w * NACC + myt * 5 + 3];
            d3 += red[w * NACC + myt * 5 + 4];
        }
        const float inv = 1.0f / sqrtf(ss * (1.0f / MH) + 1e-6f);
        const float s = scale[0];
        const float a0 = s * (d0 * inv) + base[0];
        const float a1 = s * (d1 * inv) + base[1];
        const float a2 = s * (d2 * inv) + base[2];
        const float a3 = s * (d3 * inv) + base[3];
        const float idn = 1.0f / (fabsf(a0) + fabsf(a1) + fabsf(a2) + fabsf(a3) + 1e-6f);
        float wt0 = a0 * idn, wt1 = a1 * idn, wt2 = a2 * idn, wt3 = a3 * idn;
        wA[0] = __shfl_sync(0xffffffffu, wt0, 0);
        wA[1] = __shfl_sync(0xffffffffu, wt1, 0);
        wA[2] = __shfl_sync(0xffffffffu, wt2, 0);
        wA[3] = __shfl_sync(0xffffffffu, wt3, 0);
        wB[0] = __shfl_sync(0xffffffffu, wt0, 1);
        wB[1] = __shfl_sync(0xffffffffu, wt1, 1);
        wB[2] = __shfl_sync(0xffffffffu, wt2, 1);
        wB[3] = __shfl_sync(0xffffffffu, wt3, 1);
    }

    // ------- Phase 2: pipelined queue, 3 groups of loads in flight -------
#pragma unroll
    for (int q = 0; q < NQ; q++) {
        const int t = q >> 2;
        const int g = q & 3;
        const int slot = q % 3;
        float4 a = pf[slot][0];
        float4 b = pf[slot][1];
        float4 c = pf[slot][2];
        float4 d = pf[slot][3];
        if (q + 3 < NQ)
            p2_load(x4, tok0, q + 3, tid, pf[slot]);

        const float w0 = (t == 0) ? wA[0] : wB[0];
        const float w1 = (t == 0) ? wA[1] : wB[1];
        const float w2 = (t == 0) ? wA[2] : wB[2];
        const float w3 = (t == 0) ? wA[3] : wB[3];

        unsigned qa0 = pack_bf2(a.x, a.y), qa1 = pack_bf2(a.z, a.w);
        unsigned qb0 = pack_bf2(b.x, b.y), qb1 = pack_bf2(b.z, b.w);
        unsigned qc0 = pack_bf2(c.x, c.y), qc1 = pack_bf2(c.z, c.w);
        unsigned qd0 = pack_bf2(d.x, d.y), qd1 = pack_bf2(d.z, d.w);

        float4 r;
        r.x = w0 * bflo(qa0) + w1 * bflo(qb0) + w2 * bflo(qc0) + w3 * bflo(qd0);
        r.y = w0 * bfhi(qa0) + w1 * bfhi(qb0) + w2 * bfhi(qc0) + w3 * bfhi(qd0);
        r.z = w0 * bflo(qa1) + w1 * bflo(qb1) + w2 * bflo(qc1) + w3 * bflo(qd1);
        r.w = w0 * bfhi(qa1) + w1 * bfhi(qb1) + w2 * bfhi(qc1) + w3 * bfhi(qd1);

        const int h4 = tid + g * NT;
        __stcs(reinterpret_cast<float4*>(out + (tok0 + t) * HID) + h4, r);
    }
}

extern "C" void kernel_launch(void* const* d_in, const int* in_sizes, int n_in,
                              void* d_out, int out_size) {
    const float* x     = (const float*)d_in[0];   // [T, 4*4096] fp32
    const float* fn    = (const float*)d_in[1];   // [4, 16384]  fp32
    const float* scale = (const float*)d_in[2];   // [1]
    const float* base  = (const float*)d_in[3];   // [4]
    float* out = (float*)d_out;                   // [T, 4096] fp32

    const int T = in_sizes[0] / MH;               // 8192
    hchead_kernel<<<T / TOK, NT>>>(x, fn, scale, base, out);
}

// round 17
// speedup vs baseline: 1.2890x; 1.2890x over previous
#include <cuda_runtime.h>
#include <cuda_bf16.h>

#define HID 4096
#define MH 16384             // 4 * HIDDEN
#define TOK 2
#define NT 256
#define NWARP (NT / 32)      // 8
#define NACC (TOK * 5)       // 10
#define NK (MH / 4 / NT)     // 16 float4-iterations per token
#define F4H (HID / 4)        // 1024
#define NQ (TOK * 4)         // 8 phase-2 groups (token-major)

__device__ __forceinline__ float bflo(unsigned u) {   // low bf16 -> f32
    return __uint_as_float(u << 16);
}
__device__ __forceinline__ float bfhi(unsigned u) {   // high bf16 -> f32
    return __uint_as_float(u & 0xFFFF0000u);
}
// round fp32 pair -> packed bf16x2 (RN, matches astype(bfloat16))
__device__ __forceinline__ unsigned pack_bf2(float a, float b) {
    __nv_bfloat162 p = __floats2bfloat162_rn(a, b);
    return *reinterpret_cast<unsigned*>(&p);
}

// issue the 4 stream-loads for phase-2 queue item q (t = q>>2, g = q&3)
__device__ __forceinline__ void p2_load(
    const float4* __restrict__ x4, size_t tok0, int q, int tid, float4* buf)
{
    const int t  = q >> 2;
    const int g  = q & 3;
    const int h4 = tid + g * NT;
    const float4* xp = x4 + (tok0 + t) * (MH / 4);
    buf[0] = __ldcs(xp + 0 * F4H + h4);
    buf[1] = __ldcs(xp + 1 * F4H + h4);
    buf[2] = __ldcs(xp + 2 * F4H + h4);
    buf[3] = __ldcs(xp + 3 * F4H + h4);
}

__global__ __launch_bounds__(NT, 4) void hchead_kernel(
    const float* __restrict__ x,
    const float* __restrict__ fn,
    const float* __restrict__ scale,
    const float* __restrict__ base,
    float* __restrict__ out)
{
    __shared__ float red[NWARP * NACC];
    __shared__ float wsh[TOK * 4];

    const int tid  = threadIdx.x;
    const int warp = tid >> 5, lane = tid & 31;
    const size_t tok0 = (size_t)blockIdx.x * TOK;

    const float4* x4  = reinterpret_cast<const float4*>(x);
    const float4* fn4 = reinterpret_cast<const float4*>(fn);

    // acc: t*5+0 = sum(x^2), t*5+1+m = dot with fn[m]
    float acc[NACC];
#pragma unroll
    for (int i = 0; i < NACC; i++) acc[i] = 0.f;

    // ------- Phase 1: stream x (DRAM) + fn (L2), accumulate sums -------
#pragma unroll 4
    for (int k = 0; k < NK; k++) {          // 16 iterations
        const int f = tid + k * NT;         // float4 index (j = 4f)
        const float4 g0 = fn4[0 * (MH / 4) + f];
        const float4 g1 = fn4[1 * (MH / 4) + f];
        const float4 g2 = fn4[2 * (MH / 4) + f];
        const float4 g3 = fn4[3 * (MH / 4) + f];
        float4 v0 = x4[(tok0 + 0) * (MH / 4) + f];
        float4 v1 = x4[(tok0 + 1) * (MH / 4) + f];
#pragma unroll
        for (int t = 0; t < TOK; t++) {
            const float4 v = (t == 0) ? v0 : v1;
            const unsigned p0 = pack_bf2(v.x, v.y);
            const unsigned p1 = pack_bf2(v.z, v.w);
            const float x0 = bflo(p0), x1 = bfhi(p0);
            const float x2 = bflo(p1), x3 = bfhi(p1);
            acc[t * 5 + 0] += x0 * x0 + x1 * x1 + x2 * x2 + x3 * x3;
            acc[t * 5 + 1] += x0 * g0.x + x1 * g0.y + x2 * g0.z + x3 * g0.w;
            acc[t * 5 + 2] += x0 * g1.x + x1 * g1.y + x2 * g1.z + x3 * g1.w;
            acc[t * 5 + 3] += x0 * g2.x + x1 * g2.y + x2 * g2.z + x3 * g2.w;
            acc[t * 5 + 4] += x0 * g3.x + x1 * g3.y + x2 * g3.z + x3 * g3.w;
        }
    }

    // ------- Prefetch phase-2 groups 0,1 (fly under the reduction) -------
    float4 pf[3][4];
    p2_load(x4, tok0, 0, tid, pf[0]);
    p2_load(x4, tok0, 1, tid, pf[1]);

    // ------- Warp butterfly reduction of 10 partials -------
#pragma unroll
    for (int i = 0; i < NACC; i++) {
#pragma unroll
        for (int o = 16; o > 0; o >>= 1)
            acc[i] += __shfl_xor_sync(0xffffffffu, acc[i], o);
    }
    if (lane == 0) {
#pragma unroll
        for (int i = 0; i < NACC; i++) red[warp * NACC + i] = acc[i];
    }
    __syncthreads();        // red[] published

    // ------- Prefetch group 2 (accs dead; regs free; flies under combine) ----
    p2_load(x4, tok0, 2, tid, pf[2]);

    // ------- Combine in warp 0, lanes 0..15 (short critical path) -------
    if (warp == 0) {
        const int w   = lane >> 1;          // source warp 0..7 (lanes 0..15)
        const int myt = lane & 1;           // token parity
        float v0 = 0.f, v1 = 0.f, v2 = 0.f, v3 = 0.f, v4 = 0.f;
        if (lane < 16) {
            const float* rp = red + w * NACC + myt * 5;
            v0 = rp[0]; v1 = rp[1]; v2 = rp[2]; v3 = rp[3]; v4 = rp[4];
        }
        // reduce across the 8 source warps (xor 2,4,8 preserves token parity)
#pragma unroll
        for (int o = 2; o <= 8; o <<= 1) {
            v0 += __shfl_xor_sync(0xffffffffu, v0, o);
            v1 += __shfl_xor_sync(0xffffffffu, v1, o);
            v2 += __shfl_xor_sync(0xffffffffu, v2, o);
            v3 += __shfl_xor_sync(0xffffffffu, v3, o);
            v4 += __shfl_xor_sync(0xffffffffu, v4, o);
        }
        if (lane < TOK) {                   // lanes 0,1 finish the weight math
            const float inv = 1.0f / sqrtf(v0 * (1.0f / MH) + 1e-6f);
            const float s = scale[0];
            const float a0 = s * (v1 * inv) + base[0];
            const float a1 = s * (v2 * inv) + base[1];
            const float a2 = s * (v3 * inv) + base[2];
            const float a3 = s * (v4 * inv) + base[3];
            const float idn = 1.0f / (fabsf(a0) + fabsf(a1) + fabsf(a2) + fabsf(a3) + 1e-6f);
            wsh[lane * 4 + 0] = a0 * idn;
            wsh[lane * 4 + 1] = a1 * idn;
            wsh[lane * 4 + 2] = a2 * idn;
            wsh[lane * 4 + 3] = a3 * idn;
        }
    }
    __syncthreads();

    // ------- Phase 2: pipelined queue, 3 groups of loads in flight -------
#pragma unroll
    for (int q = 0; q < NQ; q++) {
        const int t = q >> 2;
        const int g = q & 3;
        const int slot = q % 3;
        float4 a = pf[slot][0];
        float4 b = pf[slot][1];
        float4 c = pf[slot][2];
        float4 d = pf[slot][3];
        if (q + 3 < NQ)
            p2_load(x4, tok0, q + 3, tid, pf[slot]);

        const float w0 = wsh[t * 4 + 0], w1 = wsh[t * 4 + 1];
        const float w2 = wsh[t * 4 + 2], w3 = wsh[t * 4 + 3];

        unsigned qa0 = pack_bf2(a.x, a.y), qa1 = pack_bf2(a.z, a.w);
        unsigned qb0 = pack_bf2(b.x, b.y), qb1 = pack_bf2(b.z, b.w);
        unsigned qc0 = pack_bf2(c.x, c.y), qc1 = pack_bf2(c.z, c.w);
        unsigned qd0 = pack_bf2(d.x, d.y), qd1 = pack_bf2(d.z, d.w);

        float4 r;
        r.x = w0 * bflo(qa0) + w1 * bflo(qb0) + w2 * bflo(qc0) + w3 * bflo(qd0);
        r.y = w0 * bfhi(qa0) + w1 * bfhi(qb0) + w2 * bfhi(qc0) + w3 * bfhi(qd0);
        r.z = w0 * bflo(qa1) + w1 * bflo(qb1) + w2 * bflo(qc1) + w3 * bflo(qd1);
        r.w = w0 * bfhi(qa1) + w1 * bfhi(qb1) + w2 * bfhi(qc1) + w3 * bfhi(qd1);

        const int h4 = tid + g * NT;
        __stcs(reinterpret_cast<float4*>(out + (tok0 + t) * HID) + h4, r);
    }
}

extern "C" void kernel_launch(void* const* d_in, const int* in_sizes, int n_in,
                              void* d_out, int out_size) {
    const float* x     = (const float*)d_in[0];   // [T, 4*4096] fp32
    const float* fn    = (const float*)d_in[1];   // [4, 16384]  fp32
    const float* scale = (const float*)d_in[2];   // [1]
    const float* base  = (const float*)d_in[3];   // [4]
    float* out = (float*)d_out;                   // [T, 4096] fp32

    const int T = in_sizes[0] / MH;               // 8192
    hchead_kernel<<<T / TOK, NT>>>(x, fn, scale, base, out);
}